// round 17
// baseline (speedup 1.0000x reference)
#include <cuda_runtime.h>
#include <cuda_bf16.h>
#include <cstdint>

// y[b, f*C + c] = sum_hw x[b,c,hw] * kern[f,c,hw]
// B=256, F=16, C=256, HW=1024
// Grid (C=256, 2 b-halves), 256 threads (8 warps). Per CTA: GEMM M=128, N=16,
// K=1024 via mma.sync.m16n8k16 (bf16 in, fp32 accum). Warp w owns ONE m16 tile
// (b-rows w*16..w*16+15) x 2 n8 tiles -> smaller per-thread state, 3 CTAs/SM,
// 24 warps/SM for latency cover (R16 was 16 warps/SM, occ 20%).
// Precision: 2-term bf16 split of both operands, 3 MMAs per k-step -> ~6e-6.
// K chunks of 32 staged f32->bf16 in smem; pitch 80B => conflict-free LDSM.
// Register prefetch overlaps global loads with MMA compute.

#define B_DIM 256
#define F_DIM 16
#define C_DIM 256
#define HW_DIM 1024
#define KC 32
#define NCH (HW_DIM / KC)      // 32
#define THREADS 256

#define XPITCH 80              // bytes per tile row (64B data + 16B pad)
#define XHI 0                  // x hi tile: 128 rows * 80B = 10240
#define XLO 10240
#define KHI 20480              // k tiles: 16 rows * 80B = 1280
#define KLO 21760
#define SMEM_BYTES 23040

__device__ __forceinline__ uint32_t smem_u32(const void* p) {
    uint32_t a;
    asm("{ .reg .u64 t; cvta.to.shared.u64 t, %1; cvt.u32.u64 %0, t; }"
        : "=r"(a) : "l"(p));
    return a;
}

// split two floats -> packed bf16x2 hi + packed bf16x2 lo-residual
__device__ __forceinline__ void split2(float a, float b, uint32_t& hp, uint32_t& lp) {
    __nv_bfloat16 ha = __float2bfloat16_rn(a);
    __nv_bfloat16 hb = __float2bfloat16_rn(b);
    float la = a - __bfloat162float(ha);
    float lb = b - __bfloat162float(hb);
    __nv_bfloat162 h2 = __halves2bfloat162(ha, hb);
    __nv_bfloat162 l2 = __halves2bfloat162(__float2bfloat16_rn(la),
                                           __float2bfloat16_rn(lb));
    hp = *reinterpret_cast<uint32_t*>(&h2);
    lp = *reinterpret_cast<uint32_t*>(&l2);
}

__device__ __forceinline__ void ldsm4(uint32_t (&r)[4], uint32_t addr) {
    asm volatile("ldmatrix.sync.aligned.m8n8.x4.shared.b16 {%0,%1,%2,%3}, [%4];"
                 : "=r"(r[0]), "=r"(r[1]), "=r"(r[2]), "=r"(r[3]) : "r"(addr));
}

__device__ __forceinline__ void mma16816(float (&d)[4], const uint32_t (&a)[4],
                                         uint32_t b0, uint32_t b1) {
    asm volatile(
        "mma.sync.aligned.m16n8k16.row.col.f32.bf16.bf16.f32 "
        "{%0,%1,%2,%3}, {%4,%5,%6,%7}, {%8,%9}, {%0,%1,%2,%3};"
        : "+f"(d[0]), "+f"(d[1]), "+f"(d[2]), "+f"(d[3])
        : "r"(a[0]), "r"(a[1]), "r"(a[2]), "r"(a[3]), "r"(b0), "r"(b1));
}

__global__ __launch_bounds__(THREADS, 3)
void spatial_emb_mma(const float* __restrict__ x,
                     const float* __restrict__ kern,
                     float* __restrict__ out) {
    __shared__ __align__(16) char smem[SMEM_BYTES];
    const uint32_t sb = smem_u32(smem);
    const int t = threadIdx.x, w = t >> 5, l = t & 31;
    const int c = blockIdx.x, bhalf = blockIdx.y;

    // ---- staging roles
    // x: thread t -> row t>>1 (0..127), float col (t&1)*16 (4 consecutive float4)
    const float* xg = x + ((size_t)(bhalf * 128 + (t >> 1)) * C_DIM + c) * HW_DIM
                        + (size_t)(t & 1) * 16;
    const uint32_t xoff = (uint32_t)(t >> 1) * XPITCH + (uint32_t)(t & 1) * 32;
    // k (first 128 threads): row t>>3 (16 rows), float col (t&7)*4
    const bool kdo = (t < 128);
    const float* kg = kern + ((size_t)(t >> 3) * C_DIM + c) * HW_DIM
                           + (size_t)(t & 7) * 4;
    const uint32_t koff = (uint32_t)(t >> 3) * XPITCH + (uint32_t)(t & 7) * 8;

    // ---- LDSM lane addressing (mapping verified in R16)
    const int li = l & 7;
    // A x4 over warp's m16 tile: rows w*16 + ((l>>3)&1)*8 + li, col (l>>4)*16B (+s*32)
    const uint32_t rowA = (uint32_t)(w * 16 + ((l >> 3) & 1) * 8 + li);
    const uint32_t aoff = rowA * XPITCH + (uint32_t)(l >> 4) * 16;
    // B x4: f = li + (l>>4)*8, col ((l>>3)&1)*16B (+s*32)
    const uint32_t fB   = (uint32_t)(li + (l >> 4) * 8);
    const uint32_t boff = fB * XPITCH + (uint32_t)((l >> 3) & 1) * 16;

    float acc[2][4];
    #pragma unroll
    for (int nt = 0; nt < 2; nt++)
        #pragma unroll
        for (int i = 0; i < 4; i++)
            acc[nt][i] = 0.0f;

    float4 xv[4], kv;
    // prologue: load chunk 0
    #pragma unroll
    for (int q = 0; q < 4; q++)
        xv[q] = *(const float4*)(xg + q * 4);
    if (kdo) kv = *(const float4*)(kg);

    for (int ch = 0; ch < NCH; ch++) {
        // ---- convert + store chunk ch to smem tiles
        {
            uint32_t h[8], lo_[8];
            #pragma unroll
            for (int q = 0; q < 4; q++) {
                split2(xv[q].x, xv[q].y, h[2*q],   lo_[2*q]);
                split2(xv[q].z, xv[q].w, h[2*q+1], lo_[2*q+1]);
            }
            asm volatile("st.shared.v4.b32 [%0], {%1,%2,%3,%4};"
                :: "r"(sb + XHI + xoff), "r"(h[0]), "r"(h[1]), "r"(h[2]), "r"(h[3]) : "memory");
            asm volatile("st.shared.v4.b32 [%0], {%1,%2,%3,%4};"
                :: "r"(sb + XHI + xoff + 16), "r"(h[4]), "r"(h[5]), "r"(h[6]), "r"(h[7]) : "memory");
            asm volatile("st.shared.v4.b32 [%0], {%1,%2,%3,%4};"
                :: "r"(sb + XLO + xoff), "r"(lo_[0]), "r"(lo_[1]), "r"(lo_[2]), "r"(lo_[3]) : "memory");
            asm volatile("st.shared.v4.b32 [%0], {%1,%2,%3,%4};"
                :: "r"(sb + XLO + xoff + 16), "r"(lo_[4]), "r"(lo_[5]), "r"(lo_[6]), "r"(lo_[7]) : "memory");
        }
        if (kdo) {
            uint32_t h[2], lo_[2];
            split2(kv.x, kv.y, h[0], lo_[0]);
            split2(kv.z, kv.w, h[1], lo_[1]);
            asm volatile("st.shared.v2.b32 [%0], {%1,%2};"
                :: "r"(sb + KHI + koff), "r"(h[0]), "r"(h[1]) : "memory");
            asm volatile("st.shared.v2.b32 [%0], {%1,%2};"
                :: "r"(sb + KLO + koff), "r"(lo_[0]), "r"(lo_[1]) : "memory");
        }
        __syncthreads();   // tiles visible to all warps

        // ---- prefetch chunk ch+1 (flies during MMA compute)
        if (ch + 1 < NCH) {
            const float* xn = xg + (size_t)(ch + 1) * KC;
            #pragma unroll
            for (int q = 0; q < 4; q++)
                xv[q] = *(const float4*)(xn + q * 4);
            if (kdo) kv = *(const float4*)(kg + (size_t)(ch + 1) * KC);
        }

        // ---- compute: 2 k16-steps, 1 m-tile, 2 n-tiles, 3-way split
        #pragma unroll
        for (int s = 0; s < 2; s++) {
            uint32_t bh_[4], bl_[4];
            ldsm4(bh_, sb + KHI + boff + s * 32);
            ldsm4(bl_, sb + KLO + boff + s * 32);
            uint32_t ah_[4], al_[4];
            ldsm4(ah_, sb + XHI + aoff + s * 32);
            ldsm4(al_, sb + XLO + aoff + s * 32);
            mma16816(acc[0], ah_, bh_[0], bh_[1]);
            mma16816(acc[0], al_, bh_[0], bh_[1]);
            mma16816(acc[0], ah_, bl_[0], bl_[1]);
            mma16816(acc[1], ah_, bh_[2], bh_[3]);
            mma16816(acc[1], al_, bh_[2], bh_[3]);
            mma16816(acc[1], ah_, bl_[2], bl_[3]);
        }
        __syncthreads();   // all warps done reading before next overwrite
    }

    // ---- epilogue: C frag rows (l>>2, +8), cols (l&3)*2, +1 -> out[b, f*C + c]
    #pragma unroll
    for (int nt = 0; nt < 2; nt++) {
        const int b0 = bhalf * 128 + w * 16 + (l >> 2);
        const int f0 = nt * 8 + (l & 3) * 2;
        float* p0 = out + (size_t)b0 * (F_DIM * C_DIM) + (size_t)f0 * C_DIM + c;
        p0[0]     = acc[nt][0];
        p0[C_DIM] = acc[nt][1];
        float* p1 = p0 + (size_t)8 * (F_DIM * C_DIM);
        p1[0]     = acc[nt][2];
        p1[C_DIM] = acc[nt][3];
    }
}

extern "C" void kernel_launch(void* const* d_in, const int* in_sizes, int n_in,
                              void* d_out, int out_size) {
    const float* x    = (const float*)d_in[0];
    const float* kern = (const float*)d_in[1];
    float* out        = (float*)d_out;

    dim3 grid(C_DIM, 2);
    spatial_emb_mma<<<grid, THREADS>>>(x, kern, out);
}